// round 9
// baseline (speedup 1.0000x reference)
#include <cuda_runtime.h>
#include <cuda_fp16.h>
#include <cstdint>

// Problem dims (fixed by the reference)
#define BB   2
#define SS   1024
#define DD   1024
#define HH   2048
#define EE   8
#define KK   2
#define NPAIR (BB*SS*KK)   // 4096 (token, k-slot) pairs
#define MAXR  NPAIR

// ---------------- scratch (static device globals; no allocation) -------------
// NOTE: these are referenced ONLY inside device code (never passed as kernel
// args from host) — host-side references to __device__ symbols are bogus
// pointers that silently hit host shadow memory via ATS on GB300.
__device__ int   g_cnt[EE];
__device__ int   g_tok [EE * MAXR];
__device__ int   g_pair[EE * MAXR];
__device__ __half g_xh[(size_t)BB * SS * DD];
__device__ __half g_kh[(size_t)EE * HH * DD];
__device__ __half g_vh[(size_t)EE * DD * HH];
__device__ __half g_hid[(size_t)NPAIR * HH];
__device__ float  g_scr[(size_t)NPAIR * DD];

// ---------------- PTX helpers (sm_80-class only) ------------------------------
__device__ __forceinline__ uint32_t smem_u32(const void* p) {
    uint32_t a;
    asm("{ .reg .u64 t; cvta.to.shared.u64 t, %1; cvt.u32.u64 %0, t; }" : "=r"(a) : "l"(p));
    return a;
}
__device__ __forceinline__ void cp_async16(uint32_t dst, const void* src, bool valid) {
    int sz = valid ? 16 : 0;
    asm volatile("cp.async.cg.shared.global [%0], [%1], 16, %2;" :: "r"(dst), "l"(src), "r"(sz) : "memory");
}
#define CP_COMMIT() asm volatile("cp.async.commit_group;" ::: "memory")
#define CP_WAIT(N)  asm volatile("cp.async.wait_group %0;" :: "n"(N) : "memory")

__device__ __forceinline__ void ldsm4(uint32_t (&r)[4], uint32_t addr) {
    asm volatile("ldmatrix.sync.aligned.m8n8.x4.shared.b16 {%0,%1,%2,%3}, [%4];"
                 : "=r"(r[0]), "=r"(r[1]), "=r"(r[2]), "=r"(r[3]) : "r"(addr));
}
__device__ __forceinline__ void mma16816(float (&d)[4], const uint32_t (&a)[4],
                                         uint32_t b0, uint32_t b1) {
    asm volatile(
        "mma.sync.aligned.m16n8k16.row.col.f32.f16.f16.f32 "
        "{%0,%1,%2,%3}, {%4,%5,%6,%7}, {%8,%9}, {%0,%1,%2,%3};"
        : "+f"(d[0]), "+f"(d[1]), "+f"(d[2]), "+f"(d[3])
        : "r"(a[0]), "r"(a[1]), "r"(a[2]), "r"(a[3]), "r"(b0), "r"(b1));
}
__device__ __forceinline__ uint32_t sw128(uint32_t off) { return off ^ ((off >> 3) & 0x70); }

// ---------------- small kernels ----------------------------------------------
__global__ void zero_cnt_kernel() { if (threadIdx.x < EE) g_cnt[threadIdx.x] = 0; }

__global__ void bucket_kernel(const int* __restrict__ eidx) {
    int p = blockIdx.x * blockDim.x + threadIdx.x;
    if (p >= NPAIR) return;
    int token = p / KK;
    int e = eidx[p];
    int pos = atomicAdd(&g_cnt[e], 1);
    g_tok [e * MAXR + pos] = token;
    g_pair[e * MAXR + pos] = p;
}

__device__ __forceinline__ float gelu_tanh(float v) {
    const float c = 0.7978845608028654f;
    float t = tanhf(c * (v + 0.044715f * v * v * v));
    return 0.5f * v * (1.0f + t);
}

// fp32 -> fp16 convert for x and keys (destinations named in device code)
__global__ void cvt_xk_kernel(const float* __restrict__ x,
                              const float* __restrict__ keys) {
    const int XN4 = BB * SS * DD / 4;
    const int KN4 = EE * HH * DD / 4;
    int i = blockIdx.x * blockDim.x + threadIdx.x;
    const float4* src; __half* dst; int j;
    if (i < XN4)            { src = (const float4*)x;    dst = g_xh; j = i; }
    else if (i < XN4 + KN4) { src = (const float4*)keys; dst = g_kh; j = i - XN4; }
    else return;
    float4 v = src[j];
    __half2* d2 = reinterpret_cast<__half2*>(dst);
    d2[2*j]   = __floats2half2_rn(v.x, v.y);
    d2[2*j+1] = __floats2half2_rn(v.z, v.w);
}

// ---------------- HMMA grouped GEMM (fp16, fp32 accum, reg-pipelined) ---------
// C[i][n] = sum_k A[gat[i]][k] * B_e[n][k]
// CTA tile 128x128, BK=64, 3-stage cp.async ring, 256 threads, 2 CTAs/SM.
// Warps 4m x 2n, warp tile 32x64, register-double-buffered fragments.
// GEMM1 (DOGELU): extra y-slot of converter CTAs stream-converts `values`
//   fp32->fp16 into g_vh, overlapping with the GEMM.
// GEMM2 (!DOGELU): folds the expert weight ew[pair] into the epilogue.
#define A_TILE_B 16384
#define B_TILE_B 16384
#define STAGE_B  (A_TILE_B + B_TILE_B) // 32 KB
#define NSTAGE   3
#define SMEM_REQ (NSTAGE * STAGE_B)    // 96 KB

template<int NDIM, int KDIM, bool DOGELU>
__global__ void __launch_bounds__(256, 2) moe_hmma_kernel(const float* __restrict__ ew,
                                                          const float* __restrict__ vsrc) {
    const int tid = threadIdx.x;

    if (DOGELU && blockIdx.y == gridDim.y - 1) {
        // -------- converter role: values fp32 -> fp16 into g_vh (device symbol)
        const int VN4 = EE * DD * HH / 4;
        const int nconv = gridDim.x * gridDim.z;
        const int cta = blockIdx.x * gridDim.z + blockIdx.z;
        __half2* d2 = reinterpret_cast<__half2*>(g_vh);
        for (int i = cta * 256 + tid; i < VN4; i += nconv * 256) {
            float4 v = reinterpret_cast<const float4*>(vsrc)[i];
            d2[2*i]   = __floats2half2_rn(v.x, v.y);
            d2[2*i+1] = __floats2half2_rn(v.z, v.w);
        }
        return;
    }

    const int e      = blockIdx.z;
    const int n_rows = g_cnt[e];
    const int row0   = blockIdx.y * 128;
    if (row0 >= n_rows) return;
    const int col0   = blockIdx.x * 128;

    const int* gat = (DOGELU ? g_tok : g_pair) + e * MAXR;
    const int* pr  = g_pair + e * MAXR;
    const __half* A = DOGELU ? g_xh : g_hid;
    const __half* B = (DOGELU ? g_kh : g_vh) + (size_t)e * NDIM * KDIM;

    extern __shared__ char smem_dyn[];
    const uint32_t smB = smem_u32(smem_dyn);

    const int wid  = tid >> 5, lane = tid & 31;
    const int wm   = wid & 3;
    const int wn   = wid >> 2;

    // -------- cp.async: thread handles 4 A rows + 4 B rows, chunk c8 = tid&7
    const int c8    = tid & 7;
    const int rbase = tid >> 3;        // 0..31
    bool aok[4]; int aid[4]; uint32_t adst[4];
    int brow[4];  uint32_t bdst[4];
#pragma unroll
    for (int s = 0; s < 4; s++) {
        int r = rbase + 32 * s;
        uint32_t sw = sw128((uint32_t)(r * 128 + c8 * 16));
        adst[s] = sw;
        bdst[s] = A_TILE_B + sw;
        int grow = row0 + r;
        aok[s] = grow < n_rows;
        aid[s] = aok[s] ? gat[grow] : 0;
        brow[s] = col0 + r;
    }

    auto issue = [&](int stage, int buf) {
        size_t k0 = (size_t)stage * 64 + c8 * 8;
        uint32_t b = smB + (uint32_t)buf * STAGE_B;
#pragma unroll
        for (int s = 0; s < 4; s++)
            cp_async16(b + adst[s], A + (size_t)aid[s] * KDIM + k0, aok[s]);
#pragma unroll
        for (int s = 0; s < 4; s++)
            cp_async16(b + bdst[s], B + (size_t)brow[s] * KDIM + k0, true);
        CP_COMMIT();
    };

    float acc[2][8][4];
#pragma unroll
    for (int mt = 0; mt < 2; mt++)
#pragma unroll
        for (int nt = 0; nt < 8; nt++)
#pragma unroll
            for (int r = 0; r < 4; r++) acc[mt][nt][r] = 0.0f;

    // ldmatrix per-thread addressing
    const int aRowL  = wm * 32 + (lane & 15);
    const int aKHalf = (lane >> 4) * 16;
    const int bRowL  = wn * 64 + ((lane >> 4) << 3) + (lane & 7);
    const int bKHalf = ((lane >> 3) & 1) * 16;

    // double-buffered fragments
    uint32_t ah[2][2][4], bh[2][4][4];

    auto load_frags = [&](int fb, uint32_t sA, uint32_t sB, int ks) {
        const int kb = ks * 32;
#pragma unroll
        for (int mt = 0; mt < 2; mt++)
            ldsm4(ah[fb][mt], sA + sw128((uint32_t)((aRowL + mt*16) * 128 + kb + aKHalf)));
#pragma unroll
        for (int ng = 0; ng < 4; ng++)
            ldsm4(bh[fb][ng], sB + sw128((uint32_t)((bRowL + ng*16) * 128 + kb + bKHalf)));
    };
    auto do_mma = [&](int fb) {
#pragma unroll
        for (int mt = 0; mt < 2; mt++)
#pragma unroll
            for (int nt = 0; nt < 8; nt++) {
                const int ng = nt >> 1, h = (nt & 1) * 2;
                mma16816(acc[mt][nt], ah[fb][mt], bh[fb][ng][h], bh[fb][ng][h+1]);
            }
    };

    const int NS = KDIM / 64;
    issue(0, 0);
    issue(1, 1);

    for (int i = 0; i < NS; i++) {
        const int buf = i % NSTAGE;
        if (i + 1 < NS) { CP_WAIT(1); } else { CP_WAIT(0); }
        __syncthreads();
        // Safe: buffer (i+2)%3 == (i-1)%3 last read in iter i-1; all warps have
        // finished iter i-1 mma before passing this barrier (program order).
        if (i + 2 < NS) issue(i + 2, (i + 2) % NSTAGE);

        const uint32_t bb = smB + (uint32_t)buf * STAGE_B;
        const uint32_t sA = bb, sB = bb + A_TILE_B;

        load_frags(0, sA, sB, 0);
#pragma unroll
        for (int ks = 0; ks < 4; ks++) {
            if (ks < 3) load_frags((ks + 1) & 1, sA, sB, ks + 1);
            do_mma(ks & 1);
        }
    }

    // -------- epilogue: fragment rows -> scattered global rows
    int   prid[2][2];
    float wgt [2][2];
#pragma unroll
    for (int mt = 0; mt < 2; mt++)
#pragma unroll
        for (int hf = 0; hf < 2; hf++) {
            int grow = row0 + wm*32 + mt*16 + (lane >> 2) + hf*8;
            prid[mt][hf] = (grow < n_rows) ? pr[grow] : -1;
            wgt [mt][hf] = (!DOGELU && prid[mt][hf] >= 0) ? ew[prid[mt][hf]] : 1.0f;
        }

#pragma unroll
    for (int mt = 0; mt < 2; mt++)
#pragma unroll
        for (int hf = 0; hf < 2; hf++) {
            const int pid = prid[mt][hf];
            if (pid < 0) continue;
            const float w = wgt[mt][hf];
#pragma unroll
            for (int nt = 0; nt < 8; nt++) {
                const int colg = col0 + wn*64 + nt*8 + (lane & 3)*2;
                float v0 = acc[mt][nt][hf*2 + 0];
                float v1 = acc[mt][nt][hf*2 + 1];
                if (DOGELU) {
                    v0 = gelu_tanh(v0); v1 = gelu_tanh(v1);
                    *reinterpret_cast<__half2*>(g_hid + (size_t)pid * NDIM + colg) =
                        __floats2half2_rn(v0, v1);
                } else {
                    *reinterpret_cast<float2*>(g_scr + (size_t)pid * NDIM + colg) =
                        make_float2(w * v0, w * v1);
                }
            }
        }
}

// ---------------- combine: out[t] = scr[pair0] + scr[pair1] (weights folded) --
__global__ void combine_kernel(float* __restrict__ out) {
    int idx = blockIdx.x * blockDim.x + threadIdx.x;
    const int total4 = (BB * SS * DD) / 4;
    if (idx >= total4) return;
    int t  = idx / (DD / 4);
    int d4 = idx % (DD / 4);
    float4 a = reinterpret_cast<const float4*>(g_scr + (size_t)(t * KK + 0) * DD)[d4];
    float4 b = reinterpret_cast<const float4*>(g_scr + (size_t)(t * KK + 1) * DD)[d4];
    float4 r;
    r.x = a.x + b.x;
    r.y = a.y + b.y;
    r.z = a.z + b.z;
    r.w = a.w + b.w;
    reinterpret_cast<float4*>(out)[idx] = r;
}

// ---------------- entry point ---------------------------------------------------
extern "C" void kernel_launch(void* const* d_in, const int* in_sizes, int n_in,
                              void* d_out, int out_size) {
    const float* x      = (const float*)d_in[0];   // [B,S,D]
    const float* keys   = (const float*)d_in[1];   // [E,H,D]
    const float* values = (const float*)d_in[2];   // [E,D,H]
    const int*   eidx   = (const int*)  d_in[3];   // [B,S,K]
    const float* ew     = (const float*)d_in[4];   // [B,S,K]
    float* out = (float*)d_out;                    // [B,S,D]

    cudaFuncSetAttribute((const void*)moe_hmma_kernel<HH, DD, true>,
                         cudaFuncAttributeMaxDynamicSharedMemorySize, SMEM_REQ);
    cudaFuncSetAttribute((const void*)moe_hmma_kernel<DD, HH, false>,
                         cudaFuncAttributeMaxDynamicSharedMemorySize, SMEM_REQ);

    zero_cnt_kernel<<<1, 32>>>();
    bucket_kernel<<<(NPAIR + 255) / 256, 256>>>(eidx);

    const int XKN4 = (BB*SS*DD + EE*HH*DD) / 4;
    cvt_xk_kernel<<<(XKN4 + 511) / 512, 512>>>(x, keys);

    // GEMM1 + fused cvt(values): last y-slot is the converter role
    // (gridDim.x * gridDim.z = 128 converter CTAs writing g_vh).
    dim3 g1(HH / 128, MAXR / 128 + 1, EE);   // (16, 33, 8)
    moe_hmma_kernel<HH, DD, true><<<g1, 256, SMEM_REQ>>>(ew, values);

    dim3 g2(DD / 128, MAXR / 128, EE);       // (8, 32, 8)
    moe_hmma_kernel<DD, HH, false><<<g2, 256, SMEM_REQ>>>(ew, values);

    const int out4 = (BB * SS * DD) / 4;
    combine_kernel<<<(out4 + 255) / 256, 256>>>(out);
}

// round 10
// speedup vs baseline: 1.0042x; 1.0042x over previous
#include <cuda_runtime.h>
#include <cuda_fp16.h>
#include <cstdint>

// Problem dims (fixed by the reference)
#define BB   2
#define SS   1024
#define DD   1024
#define HH   2048
#define EE   8
#define KK   2
#define NPAIR (BB*SS*KK)   // 4096 (token, k-slot) pairs
#define MAXR  NPAIR

// ---------------- scratch (static device globals; no allocation) -------------
// Referenced ONLY inside device code (never passed as kernel args from host).
__device__ int   g_cnt[EE];
__device__ int   g_tok [EE * MAXR];
__device__ int   g_pair[EE * MAXR];
__device__ __half g_xh[(size_t)BB * SS * DD];
__device__ __half g_kh[(size_t)EE * HH * DD];
__device__ __half g_vh[(size_t)EE * DD * HH];
__device__ __half g_hid[(size_t)NPAIR * HH];

// ---------------- PTX helpers (sm_80-class only) ------------------------------
__device__ __forceinline__ uint32_t smem_u32(const void* p) {
    uint32_t a;
    asm("{ .reg .u64 t; cvta.to.shared.u64 t, %1; cvt.u32.u64 %0, t; }" : "=r"(a) : "l"(p));
    return a;
}
__device__ __forceinline__ void cp_async16(uint32_t dst, const void* src, bool valid) {
    int sz = valid ? 16 : 0;
    asm volatile("cp.async.cg.shared.global [%0], [%1], 16, %2;" :: "r"(dst), "l"(src), "r"(sz) : "memory");
}
#define CP_COMMIT() asm volatile("cp.async.commit_group;" ::: "memory")
#define CP_WAIT(N)  asm volatile("cp.async.wait_group %0;" :: "n"(N) : "memory")

__device__ __forceinline__ void ldsm4(uint32_t (&r)[4], uint32_t addr) {
    asm volatile("ldmatrix.sync.aligned.m8n8.x4.shared.b16 {%0,%1,%2,%3}, [%4];"
                 : "=r"(r[0]), "=r"(r[1]), "=r"(r[2]), "=r"(r[3]) : "r"(addr));
}
__device__ __forceinline__ void mma16816(float (&d)[4], const uint32_t (&a)[4],
                                         uint32_t b0, uint32_t b1) {
    asm volatile(
        "mma.sync.aligned.m16n8k16.row.col.f32.f16.f16.f32 "
        "{%0,%1,%2,%3}, {%4,%5,%6,%7}, {%8,%9}, {%0,%1,%2,%3};"
        : "+f"(d[0]), "+f"(d[1]), "+f"(d[2]), "+f"(d[3])
        : "r"(a[0]), "r"(a[1]), "r"(a[2]), "r"(a[3]), "r"(b0), "r"(b1));
}
__device__ __forceinline__ uint32_t sw128(uint32_t off) { return off ^ ((off >> 3) & 0x70); }

// ---------------- small kernels ----------------------------------------------
__global__ void zero_cnt_kernel() { if (threadIdx.x < EE) g_cnt[threadIdx.x] = 0; }

__global__ void bucket_kernel(const int* __restrict__ eidx) {
    int p = blockIdx.x * blockDim.x + threadIdx.x;
    if (p >= NPAIR) return;
    int token = p / KK;
    int e = eidx[p];
    int pos = atomicAdd(&g_cnt[e], 1);
    g_tok [e * MAXR + pos] = token;
    g_pair[e * MAXR + pos] = p;
}

__device__ __forceinline__ float gelu_tanh(float v) {
    const float c = 0.7978845608028654f;
    float t = tanhf(c * (v + 0.044715f * v * v * v));
    return 0.5f * v * (1.0f + t);
}

// fp32 -> fp16 convert for x and keys + zero-init of out (pre-GEMM2 stream order)
__global__ void cvt_xk_zero_kernel(const float* __restrict__ x,
                                   const float* __restrict__ keys,
                                   float* __restrict__ out) {
    const int XN4 = BB * SS * DD / 4;
    const int KN4 = EE * HH * DD / 4;
    const int ON4 = BB * SS * DD / 4;
    int i = blockIdx.x * blockDim.x + threadIdx.x;
    if (i < XN4) {
        float4 v = reinterpret_cast<const float4*>(x)[i];
        __half2* d2 = reinterpret_cast<__half2*>(g_xh);
        d2[2*i]   = __floats2half2_rn(v.x, v.y);
        d2[2*i+1] = __floats2half2_rn(v.z, v.w);
    } else if (i < XN4 + KN4) {
        int j = i - XN4;
        float4 v = reinterpret_cast<const float4*>(keys)[j];
        __half2* d2 = reinterpret_cast<__half2*>(g_kh);
        d2[2*j]   = __floats2half2_rn(v.x, v.y);
        d2[2*j+1] = __floats2half2_rn(v.z, v.w);
    } else if (i < XN4 + KN4 + ON4) {
        int j = i - XN4 - KN4;
        reinterpret_cast<float4*>(out)[j] = make_float4(0.f, 0.f, 0.f, 0.f);
    }
}

// ---------------- HMMA grouped GEMM (fp16, fp32 accum, reg-pipelined) ---------
// C[i][n] = sum_k A[gat[i]][k] * B_e[n][k]
// CTA tile 128x128, BK=64, 3-stage cp.async ring, 256 threads, 2 CTAs/SM.
// Warps 4m x 2n, warp tile 32x64, register-double-buffered fragments.
// GEMM1 (DOGELU): EVERY grid CTA additionally converts a 1024-float4 slice of
//   `values` fp32->fp16 into g_vh (early-exit CTAs immediately; active CTAs
//   after their epilogue). Grid is exactly 4096 CTAs = VN4/1024 slices.
// GEMM2 (!DOGELU): epilogue does out[token] += ew[pair] * v via atomicAdd
//   (exactly 2 commutative float adds per element -> deterministic).
#define A_TILE_B 16384
#define B_TILE_B 16384
#define STAGE_B  (A_TILE_B + B_TILE_B) // 32 KB
#define NSTAGE   3
#define SMEM_REQ (NSTAGE * STAGE_B)    // 96 KB

__device__ __forceinline__ void cvt_values_slice(const float* __restrict__ vsrc, int tid) {
    // grid (16,32,8) = 4096 CTAs; VN4 = 4096*1024 float4 exactly.
    const int ctaLin = (blockIdx.z * gridDim.y + blockIdx.y) * gridDim.x + blockIdx.x;
    const int base = ctaLin * 1024 + tid;            // stride 256, 4 iters
    __half2* d2 = reinterpret_cast<__half2*>(g_vh);
#pragma unroll
    for (int s = 0; s < 4; s++) {
        int i = base + s * 256;
        float4 v = reinterpret_cast<const float4*>(vsrc)[i];
        d2[2*i]   = __floats2half2_rn(v.x, v.y);
        d2[2*i+1] = __floats2half2_rn(v.z, v.w);
    }
}

template<int NDIM, int KDIM, bool DOGELU>
__global__ void __launch_bounds__(256, 2) moe_hmma_kernel(const float* __restrict__ ew,
                                                          const float* __restrict__ vsrc,
                                                          float* __restrict__ out) {
    const int tid = threadIdx.x;

    const int e      = blockIdx.z;
    const int n_rows = g_cnt[e];
    const int row0   = blockIdx.y * 128;
    if (row0 >= n_rows) {
        if (DOGELU) cvt_values_slice(vsrc, tid);
        return;
    }
    const int col0   = blockIdx.x * 128;

    const int* gat = (DOGELU ? g_tok : g_pair) + e * MAXR;
    const int* pr  = g_pair + e * MAXR;
    const __half* A = DOGELU ? g_xh : g_hid;
    const __half* B = (DOGELU ? g_kh : g_vh) + (size_t)e * NDIM * KDIM;

    extern __shared__ char smem_dyn[];
    const uint32_t smB = smem_u32(smem_dyn);

    const int wid  = tid >> 5, lane = tid & 31;
    const int wm   = wid & 3;
    const int wn   = wid >> 2;

    // -------- cp.async: thread handles 4 A rows + 4 B rows, chunk c8 = tid&7
    const int c8    = tid & 7;
    const int rbase = tid >> 3;        // 0..31
    bool aok[4]; int aid[4]; uint32_t adst[4];
    int brow[4];  uint32_t bdst[4];
#pragma unroll
    for (int s = 0; s < 4; s++) {
        int r = rbase + 32 * s;
        uint32_t sw = sw128((uint32_t)(r * 128 + c8 * 16));
        adst[s] = sw;
        bdst[s] = A_TILE_B + sw;
        int grow = row0 + r;
        aok[s] = grow < n_rows;
        aid[s] = aok[s] ? gat[grow] : 0;
        brow[s] = col0 + r;
    }

    auto issue = [&](int stage, int buf) {
        size_t k0 = (size_t)stage * 64 + c8 * 8;
        uint32_t b = smB + (uint32_t)buf * STAGE_B;
#pragma unroll
        for (int s = 0; s < 4; s++)
            cp_async16(b + adst[s], A + (size_t)aid[s] * KDIM + k0, aok[s]);
#pragma unroll
        for (int s = 0; s < 4; s++)
            cp_async16(b + bdst[s], B + (size_t)brow[s] * KDIM + k0, true);
        CP_COMMIT();
    };

    float acc[2][8][4];
#pragma unroll
    for (int mt = 0; mt < 2; mt++)
#pragma unroll
        for (int nt = 0; nt < 8; nt++)
#pragma unroll
            for (int r = 0; r < 4; r++) acc[mt][nt][r] = 0.0f;

    // ldmatrix per-thread addressing
    const int aRowL  = wm * 32 + (lane & 15);
    const int aKHalf = (lane >> 4) * 16;
    const int bRowL  = wn * 64 + ((lane >> 4) << 3) + (lane & 7);
    const int bKHalf = ((lane >> 3) & 1) * 16;

    // double-buffered fragments
    uint32_t ah[2][2][4], bh[2][4][4];

    auto load_frags = [&](int fb, uint32_t sA, uint32_t sB, int ks) {
        const int kb = ks * 32;
#pragma unroll
        for (int mt = 0; mt < 2; mt++)
            ldsm4(ah[fb][mt], sA + sw128((uint32_t)((aRowL + mt*16) * 128 + kb + aKHalf)));
#pragma unroll
        for (int ng = 0; ng < 4; ng++)
            ldsm4(bh[fb][ng], sB + sw128((uint32_t)((bRowL + ng*16) * 128 + kb + bKHalf)));
    };
    auto do_mma = [&](int fb) {
#pragma unroll
        for (int mt = 0; mt < 2; mt++)
#pragma unroll
            for (int nt = 0; nt < 8; nt++) {
                const int ng = nt >> 1, h = (nt & 1) * 2;
                mma16816(acc[mt][nt], ah[fb][mt], bh[fb][ng][h], bh[fb][ng][h+1]);
            }
    };

    const int NS = KDIM / 64;
    issue(0, 0);
    issue(1, 1);

    for (int i = 0; i < NS; i++) {
        const int buf = i % NSTAGE;
        if (i + 1 < NS) { CP_WAIT(1); } else { CP_WAIT(0); }
        __syncthreads();
        // Safe: buffer (i+2)%3 == (i-1)%3 last read in iter i-1; all warps have
        // finished iter i-1 mma before passing this barrier (program order).
        if (i + 2 < NS) issue(i + 2, (i + 2) % NSTAGE);

        const uint32_t bb = smB + (uint32_t)buf * STAGE_B;
        const uint32_t sA = bb, sB = bb + A_TILE_B;

        load_frags(0, sA, sB, 0);
#pragma unroll
        for (int ks = 0; ks < 4; ks++) {
            if (ks < 3) load_frags((ks + 1) & 1, sA, sB, ks + 1);
            do_mma(ks & 1);
        }
    }

    // -------- epilogue: fragment rows -> scattered global rows
    int   prid[2][2];
    float wgt [2][2];
#pragma unroll
    for (int mt = 0; mt < 2; mt++)
#pragma unroll
        for (int hf = 0; hf < 2; hf++) {
            int grow = row0 + wm*32 + mt*16 + (lane >> 2) + hf*8;
            prid[mt][hf] = (grow < n_rows) ? pr[grow] : -1;
            wgt [mt][hf] = (!DOGELU && prid[mt][hf] >= 0) ? ew[prid[mt][hf]] : 1.0f;
        }

#pragma unroll
    for (int mt = 0; mt < 2; mt++)
#pragma unroll
        for (int hf = 0; hf < 2; hf++) {
            const int pid = prid[mt][hf];
            if (pid < 0) continue;
            const float w = wgt[mt][hf];
#pragma unroll
            for (int nt = 0; nt < 8; nt++) {
                const int colg = col0 + wn*64 + nt*8 + (lane & 3)*2;
                float v0 = acc[mt][nt][hf*2 + 0];
                float v1 = acc[mt][nt][hf*2 + 1];
                if (DOGELU) {
                    v0 = gelu_tanh(v0); v1 = gelu_tanh(v1);
                    *reinterpret_cast<__half2*>(g_hid + (size_t)pid * NDIM + colg) =
                        __floats2half2_rn(v0, v1);
                } else {
                    // out[token, colg] += w * v ; exactly 2 commutative adds
                    // per element across the kernel -> deterministic.
                    float* dst = out + (size_t)(pid >> 1) * DD + colg;
                    atomicAdd(dst + 0, w * v0);
                    atomicAdd(dst + 1, w * v1);
                }
            }
        }

    if (DOGELU) cvt_values_slice(vsrc, tid);
}

// ---------------- entry point ---------------------------------------------------
extern "C" void kernel_launch(void* const* d_in, const int* in_sizes, int n_in,
                              void* d_out, int out_size) {
    const float* x      = (const float*)d_in[0];   // [B,S,D]
    const float* keys   = (const float*)d_in[1];   // [E,H,D]
    const float* values = (const float*)d_in[2];   // [E,D,H]
    const int*   eidx   = (const int*)  d_in[3];   // [B,S,K]
    const float* ew     = (const float*)d_in[4];   // [B,S,K]
    float* out = (float*)d_out;                    // [B,S,D]

    cudaFuncSetAttribute((const void*)moe_hmma_kernel<HH, DD, true>,
                         cudaFuncAttributeMaxDynamicSharedMemorySize, SMEM_REQ);
    cudaFuncSetAttribute((const void*)moe_hmma_kernel<DD, HH, false>,
                         cudaFuncAttributeMaxDynamicSharedMemorySize, SMEM_REQ);

    zero_cnt_kernel<<<1, 32>>>();
    bucket_kernel<<<(NPAIR + 255) / 256, 256>>>(eidx);

    const int TOT4 = (BB*SS*DD + EE*HH*DD + BB*SS*DD) / 4;
    cvt_xk_zero_kernel<<<(TOT4 + 511) / 512, 512>>>(x, keys, out);

    // GEMM1 (+ distributed cvt(values) tail work in every CTA)
    dim3 g1(HH / 128, MAXR / 128, EE);   // (16, 32, 8) = 4096 CTAs
    moe_hmma_kernel<HH, DD, true><<<g1, 256, SMEM_REQ>>>(ew, values, out);

    // GEMM2 (atomicAdd epilogue directly into out)
    dim3 g2(DD / 128, MAXR / 128, EE);   // (8, 32, 8)
    moe_hmma_kernel<DD, HH, false><<<g2, 256, SMEM_REQ>>>(ew, values, out);
}

// round 12
// speedup vs baseline: 1.0144x; 1.0101x over previous
#include <cuda_runtime.h>
#include <cuda_fp16.h>
#include <cstdint>

// Problem dims (fixed by the reference)
#define BB   2
#define SS   1024
#define DD   1024
#define HH   2048
#define EE   8
#define KK   2
#define NPAIR (BB*SS*KK)   // 4096 (token, k-slot) pairs
#define MAXR  NPAIR

// ---------------- scratch (static device globals; no allocation) -------------
// Referenced ONLY inside device code (never passed as kernel args from host).
__device__ int   g_cnt[EE];
__device__ int   g_tok [EE * MAXR];
__device__ int   g_pair[EE * MAXR];
__device__ __half g_xh[(size_t)BB * SS * DD];
__device__ __half g_kh[(size_t)EE * HH * DD];
__device__ __half g_vh[(size_t)EE * DD * HH];
__device__ __half g_hid[(size_t)NPAIR * HH];

// ---------------- PTX helpers (sm_80-class only) ------------------------------
__device__ __forceinline__ uint32_t smem_u32(const void* p) {
    uint32_t a;
    asm("{ .reg .u64 t; cvta.to.shared.u64 t, %1; cvt.u32.u64 %0, t; }" : "=r"(a) : "l"(p));
    return a;
}
__device__ __forceinline__ void cp_async16(uint32_t dst, const void* src, bool valid) {
    int sz = valid ? 16 : 0;
    asm volatile("cp.async.cg.shared.global [%0], [%1], 16, %2;" :: "r"(dst), "l"(src), "r"(sz) : "memory");
}
#define CP_COMMIT() asm volatile("cp.async.commit_group;" ::: "memory")
#define CP_WAIT(N)  asm volatile("cp.async.wait_group %0;" :: "n"(N) : "memory")

__device__ __forceinline__ void ldsm4(uint32_t (&r)[4], uint32_t addr) {
    asm volatile("ldmatrix.sync.aligned.m8n8.x4.shared.b16 {%0,%1,%2,%3}, [%4];"
                 : "=r"(r[0]), "=r"(r[1]), "=r"(r[2]), "=r"(r[3]) : "r"(addr));
}
__device__ __forceinline__ void mma16816(float (&d)[4], const uint32_t (&a)[4],
                                         uint32_t b0, uint32_t b1) {
    asm volatile(
        "mma.sync.aligned.m16n8k16.row.col.f32.f16.f16.f32 "
        "{%0,%1,%2,%3}, {%4,%5,%6,%7}, {%8,%9}, {%0,%1,%2,%3};"
        : "+f"(d[0]), "+f"(d[1]), "+f"(d[2]), "+f"(d[3])
        : "r"(a[0]), "r"(a[1]), "r"(a[2]), "r"(a[3]), "r"(b0), "r"(b1));
}
__device__ __forceinline__ uint32_t sw128(uint32_t off) { return off ^ ((off >> 3) & 0x70); }

// ---------------- small kernels ----------------------------------------------
__global__ void zero_cnt_kernel() { if (threadIdx.x < EE) g_cnt[threadIdx.x] = 0; }

__global__ void bucket_kernel(const int* __restrict__ eidx) {
    int p = blockIdx.x * blockDim.x + threadIdx.x;
    if (p >= NPAIR) return;
    int token = p / KK;
    int e = eidx[p];
    int pos = atomicAdd(&g_cnt[e], 1);
    g_tok [e * MAXR + pos] = token;
    g_pair[e * MAXR + pos] = p;
}

__device__ __forceinline__ float gelu_tanh(float v) {
    const float c = 0.7978845608028654f;
    float t = tanhf(c * (v + 0.044715f * v * v * v));
    return 0.5f * v * (1.0f + t);
}

// ONE streaming pass: fp32->fp16 for x, keys, values; zero-init out.
__global__ void cvt_all_kernel(const float* __restrict__ x,
                               const float* __restrict__ keys,
                               const float* __restrict__ values,
                               float* __restrict__ out) {
    const int XN4 = BB * SS * DD / 4;
    const int KN4 = EE * HH * DD / 4;
    const int VN4 = EE * DD * HH / 4;
    const int ON4 = BB * SS * DD / 4;
    int i = blockIdx.x * blockDim.x + threadIdx.x;
    const float4* src; __half* dst; int j;
    if (i < XN4)                  { src = (const float4*)x;      dst = g_xh; j = i; }
    else if (i < XN4+KN4)         { src = (const float4*)keys;   dst = g_kh; j = i - XN4; }
    else if (i < XN4+KN4+VN4)     { src = (const float4*)values; dst = g_vh; j = i - XN4 - KN4; }
    else if (i < XN4+KN4+VN4+ON4) {
        reinterpret_cast<float4*>(out)[i - XN4 - KN4 - VN4] = make_float4(0.f, 0.f, 0.f, 0.f);
        return;
    } else return;
    float4 v = src[j];
    __half2* d2 = reinterpret_cast<__half2*>(dst);
    d2[2*j]   = __floats2half2_rn(v.x, v.y);
    d2[2*j+1] = __floats2half2_rn(v.z, v.w);
}

// ---------------- HMMA grouped GEMM (fp16, fp32 accum, reg-pipelined) ---------
// C[i][n] = sum_k A[gat[i]][k] * B_e[n][k]
// CTA tile 128x128, BK=64, 3-stage cp.async ring, 256 threads, 2 CTAs/SM.
// Warps 4m x 2n, warp tile 32x64, register-double-buffered fragments.
// Mainloop order (proven): CP_WAIT -> __syncthreads -> issue(i+2) -> mma.
// GEMM2 (!DOGELU): epilogue does out[token] += ew[pair] * v via atomicAdd
//   (exactly 2 commutative float adds per element -> deterministic).
#define A_TILE_B 16384
#define B_TILE_B 16384
#define STAGE_B  (A_TILE_B + B_TILE_B) // 32 KB
#define NSTAGE   3
#define SMEM_REQ (NSTAGE * STAGE_B)    // 96 KB

template<int NDIM, int KDIM, bool DOGELU>
__global__ void __launch_bounds__(256, 2) moe_hmma_kernel(const float* __restrict__ ew,
                                                          float* __restrict__ out) {
    const int tid = threadIdx.x;

    const int e      = blockIdx.z;
    const int n_rows = g_cnt[e];
    const int row0   = blockIdx.y * 128;
    if (row0 >= n_rows) return;
    const int col0   = blockIdx.x * 128;

    const int* gat = (DOGELU ? g_tok : g_pair) + e * MAXR;
    const int* pr  = g_pair + e * MAXR;
    const __half* A = DOGELU ? g_xh : g_hid;
    const __half* B = (DOGELU ? g_kh : g_vh) + (size_t)e * NDIM * KDIM;

    extern __shared__ char smem_dyn[];
    const uint32_t smB = smem_u32(smem_dyn);

    const int wid  = tid >> 5, lane = tid & 31;
    const int wm   = wid & 3;
    const int wn   = wid >> 2;

    // -------- cp.async: thread handles 4 A rows + 4 B rows, chunk c8 = tid&7
    const int c8    = tid & 7;
    const int rbase = tid >> 3;        // 0..31
    bool aok[4]; int aid[4]; uint32_t adst[4];
    int brow[4];  uint32_t bdst[4];
#pragma unroll
    for (int s = 0; s < 4; s++) {
        int r = rbase + 32 * s;
        uint32_t sw = sw128((uint32_t)(r * 128 + c8 * 16));
        adst[s] = sw;
        bdst[s] = A_TILE_B + sw;
        int grow = row0 + r;
        aok[s] = grow < n_rows;
        aid[s] = aok[s] ? gat[grow] : 0;
        brow[s] = col0 + r;
    }

    auto issue = [&](int stage, int buf) {
        size_t k0 = (size_t)stage * 64 + c8 * 8;
        uint32_t b = smB + (uint32_t)buf * STAGE_B;
#pragma unroll
        for (int s = 0; s < 4; s++)
            cp_async16(b + adst[s], A + (size_t)aid[s] * KDIM + k0, aok[s]);
#pragma unroll
        for (int s = 0; s < 4; s++)
            cp_async16(b + bdst[s], B + (size_t)brow[s] * KDIM + k0, true);
        CP_COMMIT();
    };

    float acc[2][8][4];
#pragma unroll
    for (int mt = 0; mt < 2; mt++)
#pragma unroll
        for (int nt = 0; nt < 8; nt++)
#pragma unroll
            for (int r = 0; r < 4; r++) acc[mt][nt][r] = 0.0f;

    // ldmatrix per-thread addressing
    const int aRowL  = wm * 32 + (lane & 15);
    const int aKHalf = (lane >> 4) * 16;
    const int bRowL  = wn * 64 + ((lane >> 4) << 3) + (lane & 7);
    const int bKHalf = ((lane >> 3) & 1) * 16;

    // double-buffered fragments
    uint32_t ah[2][2][4], bh[2][4][4];

    auto load_frags = [&](int fb, uint32_t sA, uint32_t sB, int ks) {
        const int kb = ks * 32;
#pragma unroll
        for (int mt = 0; mt < 2; mt++)
            ldsm4(ah[fb][mt], sA + sw128((uint32_t)((aRowL + mt*16) * 128 + kb + aKHalf)));
#pragma unroll
        for (int ng = 0; ng < 4; ng++)
            ldsm4(bh[fb][ng], sB + sw128((uint32_t)((bRowL + ng*16) * 128 + kb + bKHalf)));
    };
    auto do_mma = [&](int fb) {
#pragma unroll
        for (int mt = 0; mt < 2; mt++)
#pragma unroll
            for (int nt = 0; nt < 8; nt++) {
                const int ng = nt >> 1, h = (nt & 1) * 2;
                mma16816(acc[mt][nt], ah[fb][mt], bh[fb][ng][h], bh[fb][ng][h+1]);
            }
    };

    const int NS = KDIM / 64;
    issue(0, 0);
    issue(1, 1);

    for (int i = 0; i < NS; i++) {
        const int buf = i % NSTAGE;
        if (i + 1 < NS) { CP_WAIT(1); } else { CP_WAIT(0); }
        __syncthreads();
        // Barrier after wait: makes other threads' cp.async data visible AND
        // certifies all warps finished iter i-1's mma, so refilling buffer
        // (i+2)%3 == (i-1)%3 below is safe.
        if (i + 2 < NS) issue(i + 2, (i + 2) % NSTAGE);

        const uint32_t bb = smB + (uint32_t)buf * STAGE_B;
        const uint32_t sA = bb, sB = bb + A_TILE_B;

        load_frags(0, sA, sB, 0);
#pragma unroll
        for (int ks = 0; ks < 4; ks++) {
            if (ks < 3) load_frags((ks + 1) & 1, sA, sB, ks + 1);
            do_mma(ks & 1);
        }
    }

    // -------- epilogue: fragment rows -> scattered global rows
    int   prid[2][2];
    float wgt [2][2];
#pragma unroll
    for (int mt = 0; mt < 2; mt++)
#pragma unroll
        for (int hf = 0; hf < 2; hf++) {
            int grow = row0 + wm*32 + mt*16 + (lane >> 2) + hf*8;
            prid[mt][hf] = (grow < n_rows) ? pr[grow] : -1;
            wgt [mt][hf] = (!DOGELU && prid[mt][hf] >= 0) ? ew[prid[mt][hf]] : 1.0f;
        }

#pragma unroll
    for (int mt = 0; mt < 2; mt++)
#pragma unroll
        for (int hf = 0; hf < 2; hf++) {
            const int pid = prid[mt][hf];
            if (pid < 0) continue;
            const float w = wgt[mt][hf];
#pragma unroll
            for (int nt = 0; nt < 8; nt++) {
                const int colg = col0 + wn*64 + nt*8 + (lane & 3)*2;
                float v0 = acc[mt][nt][hf*2 + 0];
                float v1 = acc[mt][nt][hf*2 + 1];
                if (DOGELU) {
                    v0 = gelu_tanh(v0); v1 = gelu_tanh(v1);
                    *reinterpret_cast<__half2*>(g_hid + (size_t)pid * NDIM + colg) =
                        __floats2half2_rn(v0, v1);
                } else {
                    // out[token, colg] += w * v ; exactly 2 commutative adds
                    // per element across the kernel -> deterministic.
                    float* dst = out + (size_t)(pid >> 1) * DD + colg;
                    atomicAdd(dst + 0, w * v0);
                    atomicAdd(dst + 1, w * v1);
                }
            }
        }
}

// ---------------- entry point ---------------------------------------------------
extern "C" void kernel_launch(void* const* d_in, const int* in_sizes, int n_in,
                              void* d_out, int out_size) {
    const float* x      = (const float*)d_in[0];   // [B,S,D]
    const float* keys   = (const float*)d_in[1];   // [E,H,D]
    const float* values = (const float*)d_in[2];   // [E,D,H]
    const int*   eidx   = (const int*)  d_in[3];   // [B,S,K]
    const float* ew     = (const float*)d_in[4];   // [B,S,K]
    float* out = (float*)d_out;                    // [B,S,D]

    cudaFuncSetAttribute((const void*)moe_hmma_kernel<HH, DD, true>,
                         cudaFuncAttributeMaxDynamicSharedMemorySize, SMEM_REQ);
    cudaFuncSetAttribute((const void*)moe_hmma_kernel<DD, HH, false>,
                         cudaFuncAttributeMaxDynamicSharedMemorySize, SMEM_REQ);

    zero_cnt_kernel<<<1, 32>>>();
    bucket_kernel<<<(NPAIR + 255) / 256, 256>>>(eidx);

    const int TOT4 = (BB*SS*DD + EE*HH*DD + EE*DD*HH + BB*SS*DD) / 4;
    cvt_all_kernel<<<(TOT4 + 511) / 512, 512>>>(x, keys, values, out);

    dim3 g1(HH / 128, MAXR / 128, EE);   // (16, 32, 8)
    moe_hmma_kernel<HH, DD, true><<<g1, 256, SMEM_REQ>>>(ew, out);

    dim3 g2(DD / 128, MAXR / 128, EE);   // (8, 32, 8)
    moe_hmma_kernel<DD, HH, false><<<g2, 256, SMEM_REQ>>>(ew, out);
}

// round 13
// speedup vs baseline: 1.0995x; 1.0840x over previous
#include <cuda_runtime.h>
#include <cuda_fp16.h>
#include <cstdint>

// Problem dims (fixed by the reference)
#define BB   2
#define SS   1024
#define DD   1024
#define HH   2048
#define EE   8
#define KK   2
#define NPAIR (BB*SS*KK)   // 4096 (token, k-slot) pairs
#define MAXR  NPAIR

// ---------------- scratch (static device globals; no allocation) -------------
// Referenced ONLY inside device code (never passed as kernel args from host).
__device__ int   g_cnt[EE];
__device__ int   g_tok [EE * MAXR];
__device__ int   g_pair[EE * MAXR];
__device__ __half g_xh[(size_t)BB * SS * DD];
__device__ __half g_kh[(size_t)EE * HH * DD];
__device__ __half g_vh[(size_t)EE * DD * HH];
__device__ __half g_hid[(size_t)NPAIR * HH];

// ---------------- PTX helpers (sm_80-class only) ------------------------------
__device__ __forceinline__ uint32_t smem_u32(const void* p) {
    uint32_t a;
    asm("{ .reg .u64 t; cvta.to.shared.u64 t, %1; cvt.u32.u64 %0, t; }" : "=r"(a) : "l"(p));
    return a;
}
__device__ __forceinline__ void cp_async16(uint32_t dst, const void* src, bool valid) {
    int sz = valid ? 16 : 0;
    asm volatile("cp.async.cg.shared.global [%0], [%1], 16, %2;" :: "r"(dst), "l"(src), "r"(sz) : "memory");
}
#define CP_COMMIT() asm volatile("cp.async.commit_group;" ::: "memory")
#define CP_WAIT(N)  asm volatile("cp.async.wait_group %0;" :: "n"(N) : "memory")

__device__ __forceinline__ void ldsm4(uint32_t (&r)[4], uint32_t addr) {
    asm volatile("ldmatrix.sync.aligned.m8n8.x4.shared.b16 {%0,%1,%2,%3}, [%4];"
                 : "=r"(r[0]), "=r"(r[1]), "=r"(r[2]), "=r"(r[3]) : "r"(addr));
}
__device__ __forceinline__ void mma16816(float (&d)[4], const uint32_t (&a)[4],
                                         uint32_t b0, uint32_t b1) {
    asm volatile(
        "mma.sync.aligned.m16n8k16.row.col.f32.f16.f16.f32 "
        "{%0,%1,%2,%3}, {%4,%5,%6,%7}, {%8,%9}, {%0,%1,%2,%3};"
        : "+f"(d[0]), "+f"(d[1]), "+f"(d[2]), "+f"(d[3])
        : "r"(a[0]), "r"(a[1]), "r"(a[2]), "r"(a[3]), "r"(b0), "r"(b1));
}
__device__ __forceinline__ uint32_t sw128(uint32_t off) { return off ^ ((off >> 3) & 0x70); }

// ---------------- small kernels ----------------------------------------------
__global__ void zero_cnt_kernel() { if (threadIdx.x < EE) g_cnt[threadIdx.x] = 0; }

__global__ void bucket_kernel(const int* __restrict__ eidx) {
    int p = blockIdx.x * blockDim.x + threadIdx.x;
    if (p >= NPAIR) return;
    int token = p / KK;
    int e = eidx[p];
    int pos = atomicAdd(&g_cnt[e], 1);
    g_tok [e * MAXR + pos] = token;
    g_pair[e * MAXR + pos] = p;
}

__device__ __forceinline__ float gelu_tanh(float v) {
    const float c = 0.7978845608028654f;
    float t = tanhf(c * (v + 0.044715f * v * v * v));
    return 0.5f * v * (1.0f + t);
}

// ONE streaming pass: fp32->fp16 for x, keys, values; zero-init out.
// Each thread: 2 float4 reads (32B) -> 1 uint4 fp16 store (16B).
__device__ __forceinline__ uint32_t pack_h2(float a, float b) {
    __half2 h = __floats2half2_rn(a, b);
    return *reinterpret_cast<uint32_t*>(&h);
}
__global__ void cvt_all_kernel(const float* __restrict__ x,
                               const float* __restrict__ keys,
                               const float* __restrict__ values,
                               float* __restrict__ out) {
    const int XN8 = BB * SS * DD / 8;
    const int KN8 = EE * HH * DD / 8;
    const int VN8 = EE * DD * HH / 8;
    const int ON8 = BB * SS * DD / 8;
    int i = blockIdx.x * blockDim.x + threadIdx.x;
    const float4* src; __half* dst; int j;
    if (i < XN8)                  { src = (const float4*)x;      dst = g_xh; j = i; }
    else if (i < XN8+KN8)         { src = (const float4*)keys;   dst = g_kh; j = i - XN8; }
    else if (i < XN8+KN8+VN8)     { src = (const float4*)values; dst = g_vh; j = i - XN8 - KN8; }
    else if (i < XN8+KN8+VN8+ON8) {
        int k = i - XN8 - KN8 - VN8;
        float4 z = make_float4(0.f, 0.f, 0.f, 0.f);
        reinterpret_cast<float4*>(out)[2*k]   = z;
        reinterpret_cast<float4*>(out)[2*k+1] = z;
        return;
    } else return;
    float4 v0 = __ldcs(src + 2*j);
    float4 v1 = __ldcs(src + 2*j + 1);
    uint4 o;
    o.x = pack_h2(v0.x, v0.y);
    o.y = pack_h2(v0.z, v0.w);
    o.z = pack_h2(v1.x, v1.y);
    o.w = pack_h2(v1.z, v1.w);
    reinterpret_cast<uint4*>(dst)[j] = o;
}

// ---------------- HMMA grouped GEMM (fp16, fp32 accum) -------------------------
// C[i][n] = sum_k A[gat[i]][k] * B_e[n][k]
// CTA tile 128x128, BK=64, 3-stage cp.async ring, **128 threads (4 warps)**,
// 2 CTAs/SM. Warps 2m x 2n, warp tile 64x64 (4 m16 x 8 n8), register-
// double-buffered fragments. 1.5x less ldmatrix traffic per MAC than 8-warp
// 32x64 layout -> smem crossbar no longer co-critical with the tensor pipe.
// Mainloop order (proven): CP_WAIT -> __syncthreads -> issue(i+2) -> mma.
// GEMM2 (!DOGELU): epilogue does out[token] += ew[pair] * v via atomicAdd
//   (exactly 2 commutative float adds per element -> deterministic).
#define A_TILE_B 16384
#define B_TILE_B 16384
#define STAGE_B  (A_TILE_B + B_TILE_B) // 32 KB
#define NSTAGE   3
#define SMEM_REQ (NSTAGE * STAGE_B)    // 96 KB

template<int NDIM, int KDIM, bool DOGELU>
__global__ void __launch_bounds__(128, 2) moe_hmma_kernel(const float* __restrict__ ew,
                                                          float* __restrict__ out) {
    const int tid = threadIdx.x;

    const int e      = blockIdx.z;
    const int n_rows = g_cnt[e];
    const int row0   = blockIdx.y * 128;
    if (row0 >= n_rows) return;
    const int col0   = blockIdx.x * 128;

    const int* gat = (DOGELU ? g_tok : g_pair) + e * MAXR;
    const int* pr  = g_pair + e * MAXR;
    const __half* A = DOGELU ? g_xh : g_hid;
    const __half* B = (DOGELU ? g_kh : g_vh) + (size_t)e * NDIM * KDIM;

    extern __shared__ char smem_dyn[];
    const uint32_t smB = smem_u32(smem_dyn);

    const int wid  = tid >> 5, lane = tid & 31;
    const int wm   = wid & 1;          // warp row -> rows [wm*64, +64)
    const int wn   = wid >> 1;         // warp col -> cols [wn*64, +64)

    // -------- cp.async: thread handles 8 A rows + 8 B rows, chunk c8 = tid&7
    const int c8    = tid & 7;
    const int rbase = tid >> 3;        // 0..15
    bool aok[8]; int aid[8]; uint32_t adst[8];
    int brow[8];  uint32_t bdst[8];
#pragma unroll
    for (int s = 0; s < 8; s++) {
        int r = rbase + 16 * s;
        uint32_t sw = sw128((uint32_t)(r * 128 + c8 * 16));
        adst[s] = sw;
        bdst[s] = A_TILE_B + sw;
        int grow = row0 + r;
        aok[s] = grow < n_rows;
        aid[s] = aok[s] ? gat[grow] : 0;
        brow[s] = col0 + r;
    }

    auto issue = [&](int stage, int buf) {
        size_t k0 = (size_t)stage * 64 + c8 * 8;
        uint32_t b = smB + (uint32_t)buf * STAGE_B;
#pragma unroll
        for (int s = 0; s < 8; s++)
            cp_async16(b + adst[s], A + (size_t)aid[s] * KDIM + k0, aok[s]);
#pragma unroll
        for (int s = 0; s < 8; s++)
            cp_async16(b + bdst[s], B + (size_t)brow[s] * KDIM + k0, true);
        CP_COMMIT();
    };

    float acc[4][8][4];
#pragma unroll
    for (int mt = 0; mt < 4; mt++)
#pragma unroll
        for (int nt = 0; nt < 8; nt++)
#pragma unroll
            for (int r = 0; r < 4; r++) acc[mt][nt][r] = 0.0f;

    // ldmatrix per-thread addressing
    const int aRowL  = wm * 64 + (lane & 15);
    const int aKHalf = (lane >> 4) * 16;
    const int bRowL  = wn * 64 + ((lane >> 4) << 3) + (lane & 7);
    const int bKHalf = ((lane >> 3) & 1) * 16;

    // double-buffered fragments
    uint32_t ah[2][4][4], bh[2][4][4];

    auto load_frags = [&](int fb, uint32_t sA, uint32_t sB, int ks) {
        const int kb = ks * 32;
#pragma unroll
        for (int mt = 0; mt < 4; mt++)
            ldsm4(ah[fb][mt], sA + sw128((uint32_t)((aRowL + mt*16) * 128 + kb + aKHalf)));
#pragma unroll
        for (int ng = 0; ng < 4; ng++)
            ldsm4(bh[fb][ng], sB + sw128((uint32_t)((bRowL + ng*16) * 128 + kb + bKHalf)));
    };
    auto do_mma = [&](int fb) {
#pragma unroll
        for (int mt = 0; mt < 4; mt++)
#pragma unroll
            for (int nt = 0; nt < 8; nt++) {
                const int ng = nt >> 1, h = (nt & 1) * 2;
                mma16816(acc[mt][nt], ah[fb][mt], bh[fb][ng][h], bh[fb][ng][h+1]);
            }
    };

    const int NS = KDIM / 64;
    issue(0, 0);
    issue(1, 1);

    for (int i = 0; i < NS; i++) {
        const int buf = i % NSTAGE;
        if (i + 1 < NS) { CP_WAIT(1); } else { CP_WAIT(0); }
        __syncthreads();
        // Barrier after wait: makes other threads' cp.async data visible AND
        // certifies all warps finished iter i-1's mma, so refilling buffer
        // (i+2)%3 == (i-1)%3 below is safe.
        if (i + 2 < NS) issue(i + 2, (i + 2) % NSTAGE);

        const uint32_t bb = smB + (uint32_t)buf * STAGE_B;
        const uint32_t sA = bb, sB = bb + A_TILE_B;

        load_frags(0, sA, sB, 0);
#pragma unroll
        for (int ks = 0; ks < 4; ks++) {
            if (ks < 3) load_frags((ks + 1) & 1, sA, sB, ks + 1);
            do_mma(ks & 1);
        }
    }

    // -------- epilogue: fragment rows -> scattered global rows
    int   prid[4][2];
    float wgt [4][2];
#pragma unroll
    for (int mt = 0; mt < 4; mt++)
#pragma unroll
        for (int hf = 0; hf < 2; hf++) {
            int grow = row0 + wm*64 + mt*16 + (lane >> 2) + hf*8;
            prid[mt][hf] = (grow < n_rows) ? pr[grow] : -1;
            wgt [mt][hf] = (!DOGELU && prid[mt][hf] >= 0) ? ew[prid[mt][hf]] : 1.0f;
        }

#pragma unroll
    for (int mt = 0; mt < 4; mt++)
#pragma unroll
        for (int hf = 0; hf < 2; hf++) {
            const int pid = prid[mt][hf];
            if (pid < 0) continue;
            const float w = wgt[mt][hf];
#pragma unroll
            for (int nt = 0; nt < 8; nt++) {
                const int colg = col0 + wn*64 + nt*8 + (lane & 3)*2;
                float v0 = acc[mt][nt][hf*2 + 0];
                float v1 = acc[mt][nt][hf*2 + 1];
                if (DOGELU) {
                    v0 = gelu_tanh(v0); v1 = gelu_tanh(v1);
                    *reinterpret_cast<__half2*>(g_hid + (size_t)pid * NDIM + colg) =
                        __floats2half2_rn(v0, v1);
                } else {
                    // out[token, colg] += w * v ; exactly 2 commutative adds
                    // per element across the kernel -> deterministic.
                    float* dst = out + (size_t)(pid >> 1) * DD + colg;
                    atomicAdd(dst + 0, w * v0);
                    atomicAdd(dst + 1, w * v1);
                }
            }
        }
}

// ---------------- entry point ---------------------------------------------------
extern "C" void kernel_launch(void* const* d_in, const int* in_sizes, int n_in,
                              void* d_out, int out_size) {
    const float* x      = (const float*)d_in[0];   // [B,S,D]
    const float* keys   = (const float*)d_in[1];   // [E,H,D]
    const float* values = (const float*)d_in[2];   // [E,D,H]
    const int*   eidx   = (const int*)  d_in[3];   // [B,S,K]
    const float* ew     = (const float*)d_in[4];   // [B,S,K]
    float* out = (float*)d_out;                    // [B,S,D]

    cudaFuncSetAttribute((const void*)moe_hmma_kernel<HH, DD, true>,
                         cudaFuncAttributeMaxDynamicSharedMemorySize, SMEM_REQ);
    cudaFuncSetAttribute((const void*)moe_hmma_kernel<DD, HH, false>,
                         cudaFuncAttributeMaxDynamicSharedMemorySize, SMEM_REQ);

    zero_cnt_kernel<<<1, 32>>>();
    bucket_kernel<<<(NPAIR + 255) / 256, 256>>>(eidx);

    const int TOT8 = (BB*SS*DD + EE*HH*DD + EE*DD*HH + BB*SS*DD) / 8;
    cvt_all_kernel<<<(TOT8 + 511) / 512, 512>>>(x, keys, values, out);

    dim3 g1(HH / 128, MAXR / 128, EE);   // (16, 32, 8)
    moe_hmma_kernel<HH, DD, true><<<g1, 128, SMEM_REQ>>>(ew, out);

    dim3 g2(DD / 128, MAXR / 128, EE);   // (8, 32, 8)
    moe_hmma_kernel<DD, HH, false><<<g2, 128, SMEM_REQ>>>(ew, out);
}